// round 3
// baseline (speedup 1.0000x reference)
#include <cuda_runtime.h>
#include <cstdint>
#include <math.h>

// ---------------- problem constants ----------------
#define T_STEPS   256
#define BATCH     1024
#define HIDN      256
#define EMBD      10
#define NCLS      10

// ---------------- launch geometry ------------------
#define CLUSTER   8
#define NCLUSTERS 16
#define GRID_X    (CLUSTER * NCLUSTERS)   // 128 CTAs
#define NTHREADS  256

#define MROWS     64                      // batch rows per cluster
#define NC        128                     // output cols per CTA = 32 kk * 4 gates
#define KTOT      (HIDN + EMBD)           // 266 (h rows + x-embedding rows)

// ---------------- smem layout (floats) -------------
#define WHS_F 0                           // Whs[KTOT][NC], j' = kk*4 + gate
#define HT_F  (KTOT * NC)                 // hT[KTOT][MROWS] (k-major, rows 256.. = x emb)
#define CS_F  (HT_F + KTOT * MROWS)       // c state [32][MROWS] (own k-slice)
#define BS_F  (CS_F + 32 * MROWS)         // bias [NC]
#define SMEMF (BS_F + NC)
#define SMEM_BYTES (SMEMF * 4)            // 212,992 bytes

// ---------------- helpers --------------------------
__device__ __forceinline__ uint32_t smem_u32(const void* p) {
    uint32_t a;
    asm("{ .reg .u64 t; cvta.to.shared.u64 t, %1; cvt.u32.u64 %0, t; }"
        : "=r"(a) : "l"(p));
    return a;
}
__device__ __forceinline__ uint32_t ctarank() {
    uint32_t r; asm("mov.u32 %0, %%cluster_ctarank;" : "=r"(r)); return r;
}
__device__ __forceinline__ uint32_t mapa_u32(uint32_t a, uint32_t r) {
    uint32_t d; asm("mapa.shared::cluster.u32 %0, %1, %2;" : "=r"(d) : "r"(a), "r"(r));
    return d;
}
__device__ __forceinline__ void cluster_sync_() {
    asm volatile("barrier.cluster.arrive.aligned;" ::: "memory");
    asm volatile("barrier.cluster.wait.aligned;" ::: "memory");
}

#define FMA2(d, a, b) asm("fma.rn.f32x2 %0, %1, %2, %0;" : "+l"(d) : "l"(a), "l"(b))

__global__ __launch_bounds__(NTHREADS, 1) __cluster_dims__(CLUSTER, 1, 1)
void lstm_kernel(const int*   __restrict__ x,
                 const float* __restrict__ emb,
                 const float* __restrict__ Wgx, const float* __restrict__ Wgh, const float* __restrict__ bg,
                 const float* __restrict__ Wix, const float* __restrict__ Wih, const float* __restrict__ bi,
                 const float* __restrict__ Wfx, const float* __restrict__ Wfh, const float* __restrict__ bf,
                 const float* __restrict__ Wox, const float* __restrict__ Woh, const float* __restrict__ bo,
                 const float* __restrict__ Wph, const float* __restrict__ bp,
                 float* __restrict__ out)
{
    extern __shared__ float smf[];
    const int      tid      = threadIdx.x;
    const uint32_t rank     = ctarank();                 // 0..7 within cluster
    const int      rowBase  = (blockIdx.x >> 3) * MROWS; // cluster id * 64
    const uint32_t smemBase = smem_u32(smf);

    // ---- Stage weights into SMEM: Whs[k][kk*4+g], k-rows 256..265 hold Wx ----
    {
        const float* Wh4[4] = {Wgh, Wih, Wfh, Woh};
        const float* Wx4[4] = {Wgx, Wix, Wfx, Wox};
        const float* b4[4]  = {bg, bi, bf, bo};
        #pragma unroll
        for (int g = 0; g < 4; ++g) {
            for (int idx = tid; idx < HIDN * 32; idx += NTHREADS) {
                int k = idx >> 5, kk = idx & 31;
                smf[WHS_F + k * NC + kk * 4 + g] = Wh4[g][k * HIDN + rank * 32 + kk];
            }
            for (int idx = tid; idx < EMBD * 32; idx += NTHREADS) {
                int e = idx >> 5, kk = idx & 31;
                smf[WHS_F + (HIDN + e) * NC + kk * 4 + g] = Wx4[g][e * HIDN + rank * 32 + kk];
            }
            if (tid < 32) smf[BS_F + tid * 4 + g] = b4[g][rank * 32 + tid];
        }
    }
    // zero h (incl. emb rows) and c
    for (int idx = tid; idx < KTOT * MROWS; idx += NTHREADS) smf[HT_F + idx] = 0.0f;
    for (int idx = tid; idx < 32 * MROWS;  idx += NTHREADS) smf[CS_F + idx] = 0.0f;
    __syncthreads();

    // GEMM thread tiling: 4 rows (m) x 8 cols (j') per thread.
    // tm selects m-group (warp-contiguous -> a-loads conflict-light),
    // tj selects j'-group (warp-broadcast b-loads).
    const int tm = tid & 15;   // m base = tm*4
    const int tj = tid >> 4;   // kk in {2tj, 2tj+1}, all 4 gates

    const uint32_t waB = smemBase + (WHS_F) * 4 + tj * 32;  // 8 floats of Whs row
    const uint32_t haB = smemBase + (HT_F) * 4 + tm * 16;   // 4 floats of hT row
    const uint32_t bsA = smemBase + (BS_F) * 4 + tj * 32;

    unsigned long long bb0, bb1, bb2, bb3;
    asm("ld.shared.v2.b64 {%0,%1},[%2];" : "=l"(bb0), "=l"(bb1) : "r"(bsA));
    asm("ld.shared.v2.b64 {%0,%1},[%2];" : "=l"(bb2), "=l"(bb3) : "r"(bsA + 16));

    for (int t = 0; t < T_STEPS; ++t) {
        // ---- gather x-embedding for this step into hT rows 256..265 ----
        if (tid < MROWS) {
            int tok = __ldg(&x[(rowBase + tid) * T_STEPS + t]);
            const float* er = emb + tok * EMBD;
            #pragma unroll
            for (int e = 0; e < EMBD; ++e)
                smf[HT_F + (HIDN + e) * MROWS + tid] = __ldg(&er[e]);
        }
        __syncthreads();

        // ---- z = bias + [h | x_emb] @ [Wh | Wx]  (packed f32x2 FMAs) ----
        unsigned long long acc[16];
        #pragma unroll
        for (int mi = 0; mi < 4; ++mi) {
            acc[mi * 4 + 0] = bb0; acc[mi * 4 + 1] = bb1;
            acc[mi * 4 + 2] = bb2; acc[mi * 4 + 3] = bb3;
        }

        #pragma unroll 2
        for (int k = 0; k < KTOT; ++k) {
            unsigned long long b0, b1, b2, b3;
            uint32_t wa = waB + (uint32_t)k * (NC * 4);
            asm("ld.shared.v2.b64 {%0,%1},[%2];" : "=l"(b0), "=l"(b1) : "r"(wa));
            asm("ld.shared.v2.b64 {%0,%1},[%2];" : "=l"(b2), "=l"(b3) : "r"(wa + 16));
            float a0, a1, a2, a3;
            asm("ld.shared.v4.f32 {%0,%1,%2,%3},[%4];"
                : "=f"(a0), "=f"(a1), "=f"(a2), "=f"(a3)
                : "r"(haB + (uint32_t)k * (MROWS * 4)));
            unsigned long long p0, p1, p2, p3;
            asm("mov.b64 %0,{%1,%1};" : "=l"(p0) : "f"(a0));
            asm("mov.b64 %0,{%1,%1};" : "=l"(p1) : "f"(a1));
            asm("mov.b64 %0,{%1,%1};" : "=l"(p2) : "f"(a2));
            asm("mov.b64 %0,{%1,%1};" : "=l"(p3) : "f"(a3));
            FMA2(acc[0],  p0, b0); FMA2(acc[1],  p0, b1); FMA2(acc[2],  p0, b2); FMA2(acc[3],  p0, b3);
            FMA2(acc[4],  p1, b0); FMA2(acc[5],  p1, b1); FMA2(acc[6],  p1, b2); FMA2(acc[7],  p1, b3);
            FMA2(acc[8],  p2, b0); FMA2(acc[9],  p2, b1); FMA2(acc[10], p2, b2); FMA2(acc[11], p2, b3);
            FMA2(acc[12], p3, b0); FMA2(acc[13], p3, b1); FMA2(acc[14], p3, b2); FMA2(acc[15], p3, b3);
        }

        // ---- gates + state update (all 4 gates are register-local per (m,kk)) ----
        float h0[4], h1[4];
        #pragma unroll
        for (int mi = 0; mi < 4; ++mi) {
            #pragma unroll
            for (int kkl = 0; kkl < 2; ++kkl) {
                float zg, zi2, zf, zo;
                asm("mov.b64 {%0,%1},%2;" : "=f"(zg), "=f"(zi2) : "l"(acc[mi * 4 + kkl * 2 + 0]));
                asm("mov.b64 {%0,%1},%2;" : "=f"(zf), "=f"(zo)  : "l"(acc[mi * 4 + kkl * 2 + 1]));
                float gg = tanhf(zg);
                float ii = 1.0f / (1.0f + expf(-zi2));
                float ff = 1.0f / (1.0f + expf(-zf));
                float oo = 1.0f / (1.0f + expf(-zo));
                int kk = 2 * tj + kkl;
                int m  = tm * 4 + mi;
                float cold = smf[CS_F + kk * MROWS + m];
                float cn = gg * ii + cold * ff;
                smf[CS_F + kk * MROWS + m] = cn;
                float hn = tanhf(cn) * oo;
                if (kkl == 0) h0[mi] = hn; else h1[mi] = hn;
            }
        }

        // all CTAs must be done READING hT before anyone overwrites it
        cluster_sync_();

        // ---- broadcast our 32 h-columns to all 8 cluster SMEM replicas ----
        {
            uint32_t own = smemBase +
                (uint32_t)(HT_F + (rank * 32 + 2 * tj) * MROWS + tm * 4) * 4;
            #pragma unroll
            for (int p = 0; p < CLUSTER; ++p) {
                uint32_t pa = mapa_u32(own, (uint32_t)p);
                asm volatile("st.shared::cluster.v4.f32 [%0],{%1,%2,%3,%4};"
                             :: "r"(pa), "f"(h0[0]), "f"(h0[1]), "f"(h0[2]), "f"(h0[3]) : "memory");
                asm volatile("st.shared::cluster.v4.f32 [%0],{%1,%2,%3,%4};"
                             :: "r"(pa + MROWS * 4), "f"(h1[0]), "f"(h1[1]), "f"(h1[2]), "f"(h1[3]) : "memory");
            }
        }

        // h(t) fully exchanged & visible
        cluster_sync_();
    }

    // ---- final projection: out = h_T @ Wph + bp  (each CTA: 8 rows x 10 cls) ----
    if (tid < 8 * NCLS) {
        int mi = tid / NCLS, cl = tid - mi * NCLS;
        int m  = (int)rank * 8 + mi;
        float s = __ldg(&bp[cl]);
        #pragma unroll 4
        for (int k = 0; k < HIDN; ++k)
            s += smf[HT_F + k * MROWS + m] * __ldg(&Wph[k * NCLS + cl]);
        out[(rowBase + m) * NCLS + cl] = s;
    }
}

// ---------------- host launch ----------------------
extern "C" void kernel_launch(void* const* d_in, const int* in_sizes, int n_in,
                              void* d_out, int out_size)
{
    const int*   x   = (const int*)  d_in[0];
    const float* emb = (const float*)d_in[1];
    const float* Wgx = (const float*)d_in[2];
    const float* Wgh = (const float*)d_in[3];
    const float* bg  = (const float*)d_in[4];
    const float* Wix = (const float*)d_in[5];
    const float* Wih = (const float*)d_in[6];
    const float* bi  = (const float*)d_in[7];
    const float* Wfx = (const float*)d_in[8];
    const float* Wfh = (const float*)d_in[9];
    const float* bf  = (const float*)d_in[10];
    const float* Wox = (const float*)d_in[11];
    const float* Woh = (const float*)d_in[12];
    const float* bo  = (const float*)d_in[13];
    const float* Wph = (const float*)d_in[14];
    const float* bp  = (const float*)d_in[15];

    cudaFuncSetAttribute(lstm_kernel,
                         cudaFuncAttributeMaxDynamicSharedMemorySize, SMEM_BYTES);

    lstm_kernel<<<GRID_X, NTHREADS, SMEM_BYTES>>>(
        x, emb, Wgx, Wgh, bg, Wix, Wih, bi, Wfx, Wfh, bf, Wox, Woh, bo,
        Wph, bp, (float*)d_out);
}

// round 5
// speedup vs baseline: 1.7877x; 1.7877x over previous
#include <cuda_runtime.h>
#include <cuda_fp16.h>
#include <cstdint>

// ---------------- problem constants ----------------
#define T_STEPS 256
#define HID     256
#define EMBD    10
#define NCLS    10

// ---------------- geometry -------------------------
#define CLUSTER  8
#define GRID_X   128            // 16 clusters x 8 CTAs
#define NTHREADS 256
#define MROWS    64             // batch rows per cluster
// per-CTA GEMM: M=64, N=128 (j' = g*32+kk), K=272 (256 h + 16 x)

// ---------------- smem layout (bytes) --------------
#define KPAD  280               // halfs per row (k 0..271 used, pad for LDSM banks)
#define STRB  (KPAD * 2)        // 560 B row stride
#define OFF_WHI 0
#define W_SZ   (128 * STRB)     // 71,680
#define OFF_WLO (OFF_WHI + W_SZ)
#define OFF_AHI (OFF_WLO + W_SZ)      // 143,360
#define A_SZ   (64 * STRB)      // 35,840
#define OFF_ALO (OFF_AHI + A_SZ)
#define OFF_ZB  OFF_AHI               // zbuf [128][65] f32 = 33,280 aliases A_hi
#define OFF_BIAS (OFF_ALO + A_SZ)     // 215,040 : 128 f32
#define SMEM_BYTES (OFF_BIAS + 512)   // 215,552

// h exchange: packed (lo<<16 | hi) fp16, double-buffered
__device__ uint32_t Gbuf[2][1024][HID];

// ---------------- helpers --------------------------
__device__ __forceinline__ uint32_t smem_u32(const void* p) {
    uint32_t a;
    asm("{ .reg .u64 t; cvta.to.shared.u64 t, %1; cvt.u32.u64 %0, t; }" : "=r"(a) : "l"(p));
    return a;
}
__device__ __forceinline__ uint32_t ctarank() {
    uint32_t r; asm("mov.u32 %0, %%cluster_ctarank;" : "=r"(r)); return r;
}
__device__ __forceinline__ void cluster_sync_() {
    asm volatile("barrier.cluster.arrive.aligned;" ::: "memory");
    asm volatile("barrier.cluster.wait.aligned;" ::: "memory");
}

#define LDSM4(R, ADDR)                                                          \
    asm volatile("ldmatrix.sync.aligned.m8n8.x4.shared.b16 {%0,%1,%2,%3},[%4];" \
                 : "=r"((R)[0]), "=r"((R)[1]), "=r"((R)[2]), "=r"((R)[3])       \
                 : "r"(ADDR))

#define MMA(D, A, B0, B1)                                                       \
    asm volatile("mma.sync.aligned.m16n8k16.row.col.f32.f16.f16.f32 "           \
                 "{%0,%1,%2,%3},{%4,%5,%6,%7},{%8,%9},{%0,%1,%2,%3};"           \
                 : "+f"((D)[0]), "+f"((D)[1]), "+f"((D)[2]), "+f"((D)[3])       \
                 : "r"((A)[0]), "r"((A)[1]), "r"((A)[2]), "r"((A)[3]),          \
                   "r"(B0), "r"(B1))

__device__ __forceinline__ float sigm(float x) {
    float e, r;
    asm("ex2.approx.f32 %0,%1;" : "=f"(e) : "f"(-x * 1.4426950408889634f));
    asm("rcp.approx.f32 %0,%1;" : "=f"(r) : "f"(1.0f + e));
    return r;
}
__device__ __forceinline__ float tanh_(float x) { return fmaf(2.0f, sigm(2.0f * x), -1.0f); }

__device__ __forceinline__ void sts_h16(uint32_t addr, __half v) {
    asm volatile("st.shared.b16 [%0], %1;" :: "r"(addr), "h"(__half_as_ushort(v)) : "memory");
}
__device__ __forceinline__ void split16(float v, __half& hi, __half& lo) {
    hi = __float2half_rn(v);
    lo = __float2half_rn(v - __half2float(hi));
}

// stage x-embedding for step t into A rows k=256..271 (hi & lo)
__device__ __forceinline__ void stage_x(const int* __restrict__ x,
                                        const float* __restrict__ emb,
                                        int clusterRow, int t, int tid, uint32_t sb) {
    if (tid < 128) {
        int m = tid >> 1, half = tid & 1;
        int tok = __ldg(&x[(clusterRow + m) * T_STEPS + t]);
        const float* er = emb + (long)tok * EMBD + half * 5;
        uint32_t ab = sb + OFF_AHI + (uint32_t)m * STRB;
        #pragma unroll
        for (int e = 0; e < 5; ++e) {
            float v = __ldg(er + e);
            __half hi, lo; split16(v, hi, lo);
            uint32_t o = (uint32_t)((256 + half * 5 + e) * 2);
            sts_h16(ab + o, hi);
            sts_h16(ab + A_SZ + o, lo);
        }
        // zero k = 266..271 (clobbered by zbuf alias each step)
        #pragma unroll
        for (int e = 0; e < 3; ++e) {
            uint32_t o = (uint32_t)((266 + half * 3 + e) * 2);
            sts_h16(ab + o, __ushort_as_half(0));
            sts_h16(ab + A_SZ + o, __ushort_as_half(0));
        }
    }
}

__global__ __launch_bounds__(NTHREADS, 1) __cluster_dims__(CLUSTER, 1, 1)
void lstm_hmma_kernel(const int*   __restrict__ x,   const float* __restrict__ emb,
                      const float* __restrict__ Wgx, const float* __restrict__ Wgh, const float* __restrict__ bg,
                      const float* __restrict__ Wix, const float* __restrict__ Wih, const float* __restrict__ bi,
                      const float* __restrict__ Wfx, const float* __restrict__ Wfh, const float* __restrict__ bf,
                      const float* __restrict__ Wox, const float* __restrict__ Woh, const float* __restrict__ bo,
                      const float* __restrict__ Wph, const float* __restrict__ bp,
                      float* __restrict__ out)
{
    extern __shared__ char smem[];
    const int      tid  = threadIdx.x;
    const int      lane = tid & 31;
    const int      w    = tid >> 5;
    const uint32_t rank = ctarank();                  // 0..7
    const int clusterRow = (blockIdx.x >> 3) * MROWS; // cluster id * 64
    const uint32_t sb = smem_u32(smem);

    // ---------- zero W+A regions ----------
    for (int i = tid; i < OFF_BIAS / 4; i += NTHREADS)
        *(uint32_t*)(smem + i * 4) = 0u;
    __syncthreads();

    // ---------- stage W (hi/lo), bias ----------
    {
        const float* Wh4[4] = {Wgh, Wih, Wfh, Woh};
        const float* Wx4[4] = {Wgx, Wix, Wfx, Wox};
        const float* b4[4]  = {bg, bi, bf, bo};
        #pragma unroll
        for (int g = 0; g < 4; ++g) {
            for (int idx = tid; idx < 32 * HID; idx += NTHREADS) {
                int kk = idx & 31, k = idx >> 5;
                int j = g * 32 + kk;
                float v = Wh4[g][k * HID + (int)rank * 32 + kk];
                __half hi, lo; split16(v, hi, lo);
                uint32_t o = (uint32_t)j * STRB + (uint32_t)(k * 2);
                sts_h16(sb + OFF_WHI + o, hi);
                sts_h16(sb + OFF_WLO + o, lo);
            }
            for (int idx = tid; idx < 32 * EMBD; idx += NTHREADS) {
                int kk = idx & 31, e = idx >> 5;
                int j = g * 32 + kk;
                float v = Wx4[g][e * HID + (int)rank * 32 + kk];
                __half hi, lo; split16(v, hi, lo);
                uint32_t o = (uint32_t)j * STRB + (uint32_t)((256 + e) * 2);
                sts_h16(sb + OFF_WHI + o, hi);
                sts_h16(sb + OFF_WLO + o, lo);
            }
            if (tid < 32)
                *(float*)(smem + OFF_BIAS + (g * 32 + tid) * 4) = b4[g][(int)rank * 32 + tid];
        }
    }
    stage_x(x, emb, clusterRow, 0, tid, sb);   // x for t=0 (A_h part is zero)
    __syncthreads();

    // ---------- GEMM thread mapping ----------
    const int mg = w & 1;          // m group: rows mg*32..+31
    const int ng = w >> 1;         // n group: j' ng*32..+31
    const uint32_t laneOff = (uint32_t)(((((lane >> 3) & 1) * 8 + (lane & 7)) * STRB) + ((lane >> 4) * 16));
    const uint32_t aHiB = sb + OFF_AHI + (uint32_t)(mg * 32) * STRB + laneOff;
    const uint32_t aLoB = aHiB + A_SZ;
    const uint32_t bHiB = sb + OFF_WHI + (uint32_t)(ng * 32) * STRB + laneOff;
    const uint32_t bLoB = bHiB + W_SZ;

    float* zb = (float*)(smem + OFF_ZB);            // [128][65] f32
    const float* bias = (const float*)(smem + OFF_BIAS);
    const int dm = lane >> 2, dj = 2 * (lane & 3);  // d-frag lane coords
    const int em = tid & 63, ekkg = tid >> 6;       // epilogue cell mapping

    float c8[8];
    #pragma unroll
    for (int i = 0; i < 8; ++i) c8[i] = 0.0f;

    for (int t = 0; t < T_STEPS; ++t) {
        __syncthreads();   // A staged (exchange/x of previous iteration)

        // ---------------- GEMM ----------------
        float d[2][4][4];
        #pragma unroll
        for (int a = 0; a < 2; ++a)
            #pragma unroll
            for (int b = 0; b < 4; ++b)
                #pragma unroll
                for (int c = 0; c < 4; ++c) d[a][b][c] = 0.0f;

        #pragma unroll 1
        for (int kc = 0; kc < 17; ++kc) {
            const uint32_t ka = (uint32_t)kc * 32;
            uint32_t ah0[4], ah1[4], al0[4], al1[4];
            uint32_t bh0[4], bh1[4], bl0[4], bl1[4];
            LDSM4(ah0, aHiB + ka); LDSM4(ah1, aHiB + ka + 16 * STRB);
            LDSM4(al0, aLoB + ka); LDSM4(al1, aLoB + ka + 16 * STRB);
            LDSM4(bh0, bHiB + ka); LDSM4(bh1, bHiB + ka + 16 * STRB);
            LDSM4(bl0, bLoB + ka); LDSM4(bl1, bLoB + ka + 16 * STRB);
            #pragma unroll
            for (int mt = 0; mt < 2; ++mt) {
                uint32_t* ah = mt ? ah1 : ah0;
                uint32_t* al = mt ? al1 : al0;
                #pragma unroll
                for (int nt = 0; nt < 4; ++nt) {
                    uint32_t* bh = (nt < 2) ? bh0 : bh1;
                    uint32_t* bl = (nt < 2) ? bl0 : bl1;
                    const int s = nt & 1;
                    MMA(d[mt][nt], ah, bh[s], bh[s + 2]);
                    MMA(d[mt][nt], ah, bl[s], bl[s + 2]);
                    MMA(d[mt][nt], al, bh[s], bh[s + 2]);
                }
            }
        }
        __syncthreads();   // everyone done reading A (zbuf aliases A_hi)

        // ---------------- d -> zbuf ----------------
        #pragma unroll
        for (int mt = 0; mt < 2; ++mt) {
            #pragma unroll
            for (int nt = 0; nt < 4; ++nt) {
                int m0 = mg * 32 + mt * 16 + dm;
                int j0 = ng * 32 + nt * 8 + dj;
                zb[j0 * 65 + m0]           = d[mt][nt][0];
                zb[(j0 + 1) * 65 + m0]     = d[mt][nt][1];
                zb[j0 * 65 + m0 + 8]       = d[mt][nt][2];
                zb[(j0 + 1) * 65 + m0 + 8] = d[mt][nt][3];
            }
        }
        __syncthreads();

        // ---------------- epilogue ----------------
        {
            uint32_t hw[8];
            #pragma unroll
            for (int q = 0; q < 8; ++q) {
                int kk = ekkg * 8 + q;
                float zg = zb[kk * 65 + em]         + bias[kk];
                float zi = zb[(32 + kk) * 65 + em]  + bias[32 + kk];
                float zf = zb[(64 + kk) * 65 + em]  + bias[64 + kk];
                float zo = zb[(96 + kk) * 65 + em]  + bias[96 + kk];
                float gg = tanh_(zg);
                float ii = sigm(zi);
                float ff = sigm(zf);
                float oo = sigm(zo);
                float cn = fmaf(gg, ii, c8[q] * ff);
                c8[q] = cn;
                float hn = tanh_(cn) * oo;
                __half hi, lo; split16(hn, hi, lo);
                hw[q] = (uint32_t)__half_as_ushort(hi) | ((uint32_t)__half_as_ushort(lo) << 16);
            }
            uint32_t* gd = &Gbuf[t & 1][clusterRow + em][(int)rank * 32 + ekkg * 8];
            __stcg((uint4*)(gd + 0), make_uint4(hw[0], hw[1], hw[2], hw[3]));
            __stcg((uint4*)(gd + 4), make_uint4(hw[4], hw[5], hw[6], hw[7]));
            __threadfence();
        }

        cluster_sync_();   // zbuf reads done + all CTAs' h globally visible

        // ---------------- exchange + x(t+1) ----------------
        if (t != T_STEPS - 1) {
            const uint32_t* gs = &Gbuf[t & 1][clusterRow][0];
            #pragma unroll 4
            for (int i = 0; i < 16; ++i) {
                int chunk = tid + i * NTHREADS;       // 4096 uint4 total
                int row = chunk >> 6;
                int c4  = chunk & 63;
                uint4 v = __ldcg((const uint4*)(gs + row * HID + c4 * 4));
                uint32_t hi01 = __byte_perm(v.x, v.y, 0x5410);
                uint32_t hi23 = __byte_perm(v.z, v.w, 0x5410);
                uint32_t lo01 = __byte_perm(v.x, v.y, 0x7632);
                uint32_t lo23 = __byte_perm(v.z, v.w, 0x7632);
                uint32_t o = (uint32_t)row * STRB + (uint32_t)(c4 * 8);
                asm volatile("st.shared.v2.b32 [%0], {%1,%2};"
                             :: "r"(sb + OFF_AHI + o), "r"(hi01), "r"(hi23) : "memory");
                asm volatile("st.shared.v2.b32 [%0], {%1,%2};"
                             :: "r"(sb + OFF_ALO + o), "r"(lo01), "r"(lo23) : "memory");
            }
            stage_x(x, emb, clusterRow, t + 1, tid, sb);
        }
    }

    // ---------------- final projection ----------------
    if (tid < 8 * NCLS) {
        int mi = tid / NCLS, cl = tid - mi * NCLS;
        int m  = (int)rank * 8 + mi;
        const uint32_t* hr = &Gbuf[1][clusterRow + m][0];
        float s = __ldg(&bp[cl]);
        #pragma unroll 4
        for (int k = 0; k < HID; ++k) {
            uint32_t v = __ldcg(&hr[k]);
            float hv = __half2float(__ushort_as_half((unsigned short)(v & 0xFFFFu)))
                     + __half2float(__ushort_as_half((unsigned short)(v >> 16)));
            s = fmaf(hv, __ldg(&Wph[k * NCLS + cl]), s);
        }
        out[(clusterRow + m) * NCLS + cl] = s;
    }
}

// ---------------- host launch ----------------------
extern "C" void kernel_launch(void* const* d_in, const int* in_sizes, int n_in,
                              void* d_out, int out_size)
{
    const int*   x   = (const int*)  d_in[0];
    const float* emb = (const float*)d_in[1];
    const float* Wgx = (const float*)d_in[2];
    const float* Wgh = (const float*)d_in[3];
    const float* bg  = (const float*)d_in[4];
    const float* Wix = (const float*)d_in[5];
    const float* Wih = (const float*)d_in[6];
    const float* bi  = (const float*)d_in[7];
    const float* Wfx = (const float*)d_in[8];
    const float* Wfh = (const float*)d_in[9];
    const float* bf  = (const float*)d_in[10];
    const float* Wox = (const float*)d_in[11];
    const float* Woh = (const float*)d_in[12];
    const float* bo  = (const float*)d_in[13];
    const float* Wph = (const float*)d_in[14];
    const float* bp  = (const float*)d_in[15];

    cudaFuncSetAttribute(lstm_hmma_kernel,
                         cudaFuncAttributeMaxDynamicSharedMemorySize, SMEM_BYTES);

    lstm_hmma_kernel<<<GRID_X, NTHREADS, SMEM_BYTES>>>(
        x, emb, Wgx, Wgh, bg, Wix, Wih, bi, Wfx, Wfh, bf, Wox, Woh, bo,
        Wph, bp, (float*)d_out);
}

// round 7
// speedup vs baseline: 1.8044x; 1.0094x over previous
#include <cuda_runtime.h>
#include <cuda_fp16.h>
#include <cstdint>

// ---------------- problem constants ----------------
#define T_STEPS 256
#define HID     256
#define EMBD    10
#define NCLS    10

// ---------------- geometry -------------------------
#define CLUSTER  8
#define GRID_X   128            // 16 clusters x 8 CTAs
#define NTHREADS 256
#define MROWS    64             // batch rows per cluster
// per-CTA GEMM: M=64, N=128 (permuted j'), K=272 (256 h + 10 x + 2 bias)

// ---------------- smem layout (bytes) --------------
#define KPAD  280               // halfs per row
#define STRB  (KPAD * 2)        // 560 B row stride
#define OFF_WHI 0
#define W_SZ   (128 * STRB)     // 71,680
#define OFF_WLO (OFF_WHI + W_SZ)
#define OFF_AHI (OFF_WLO + W_SZ)      // 143,360
#define A_SZ   (64 * STRB)            // 35,840
#define OFF_ALO (OFF_AHI + A_SZ)
#define SMEM_BYTES (OFF_ALO + A_SZ)   // 215,040

// ---------------- helpers --------------------------
__device__ __forceinline__ uint32_t smem_u32(const void* p) {
    uint32_t a;
    asm("{ .reg .u64 t; cvta.to.shared.u64 t, %1; cvt.u32.u64 %0, t; }" : "=r"(a) : "l"(p));
    return a;
}
__device__ __forceinline__ uint32_t ctarank() {
    uint32_t r; asm("mov.u32 %0, %%cluster_ctarank;" : "=r"(r)); return r;
}
__device__ __forceinline__ uint32_t mapa_u32(uint32_t a, uint32_t r) {
    uint32_t d; asm("mapa.shared::cluster.u32 %0, %1, %2;" : "=r"(d) : "r"(a), "r"(r));
    return d;
}
__device__ __forceinline__ void cluster_arrive_() {
    asm volatile("barrier.cluster.arrive.aligned;" ::: "memory");
}
__device__ __forceinline__ void cluster_wait_() {
    asm volatile("barrier.cluster.wait.aligned;" ::: "memory");
}

#define LDSM4(R, ADDR)                                                          \
    asm volatile("ldmatrix.sync.aligned.m8n8.x4.shared.b16 {%0,%1,%2,%3},[%4];" \
                 : "=r"((R)[0]), "=r"((R)[1]), "=r"((R)[2]), "=r"((R)[3])       \
                 : "r"(ADDR))

#define MMA(D, A, B0, B1)                                                       \
    asm volatile("mma.sync.aligned.m16n8k16.row.col.f32.f16.f16.f32 "           \
                 "{%0,%1,%2,%3},{%4,%5,%6,%7},{%8,%9},{%0,%1,%2,%3};"           \
                 : "+f"((D)[0]), "+f"((D)[1]), "+f"((D)[2]), "+f"((D)[3])       \
                 : "r"((A)[0]), "r"((A)[1]), "r"((A)[2]), "r"((A)[3]),          \
                   "r"(B0), "r"(B1))

__device__ __forceinline__ float sigm(float x) {
    float e, r;
    asm("ex2.approx.f32 %0,%1;" : "=f"(e) : "f"(-x * 1.4426950408889634f));
    asm("rcp.approx.f32 %0,%1;" : "=f"(r) : "f"(1.0f + e));
    return r;
}
__device__ __forceinline__ float tanh_(float x) { return fmaf(2.0f, sigm(2.0f * x), -1.0f); }

__device__ __forceinline__ void sts_h16(uint32_t addr, __half v) {
    asm volatile("st.shared.b16 [%0], %1;" :: "r"(addr), "h"(__half_as_ushort(v)) : "memory");
}
__device__ __forceinline__ void split16(float v, __half& hi, __half& lo) {
    hi = __float2half_rn(v);
    lo = __float2half_rn(v - __half2float(hi));
}

// column permutation: all 4 gates of one kk inside one n8 tile, lane-pair local
__device__ __forceinline__ int jprime(int kk, int g) {
    return ((kk >> 3) << 5) + ((kk & 3) << 3) + (((kk >> 2) & 1) << 2) + g;
}

// stage x-embedding for step t into A rows k=256..265 (hi & lo)
__device__ __forceinline__ void stage_x(const int* __restrict__ x,
                                        const float* __restrict__ emb,
                                        int clusterRow, int t, int tid, uint32_t sb) {
    if (tid < 128) {
        int m = tid >> 1, half = tid & 1;
        int tok = __ldg(&x[(clusterRow + m) * T_STEPS + t]);
        const float* er = emb + (long)tok * EMBD + half * 5;
        uint32_t ab = sb + OFF_AHI + (uint32_t)m * STRB;
        #pragma unroll
        for (int e = 0; e < 5; ++e) {
            float v = __ldg(er + e);
            __half hi, lo; split16(v, hi, lo);
            uint32_t o = (uint32_t)((256 + half * 5 + e) * 2);
            sts_h16(ab + o, hi);
            sts_h16(ab + A_SZ + o, lo);
        }
    }
}

__global__ __launch_bounds__(NTHREADS, 1) __cluster_dims__(CLUSTER, 1, 1)
void lstm_hmma_kernel(const int*   __restrict__ x,   const float* __restrict__ emb,
                      const float* __restrict__ Wgx, const float* __restrict__ Wgh, const float* __restrict__ bg,
                      const float* __restrict__ Wix, const float* __restrict__ Wih, const float* __restrict__ bi,
                      const float* __restrict__ Wfx, const float* __restrict__ Wfh, const float* __restrict__ bf,
                      const float* __restrict__ Wox, const float* __restrict__ Woh, const float* __restrict__ bo,
                      const float* __restrict__ Wph, const float* __restrict__ bp,
                      float* __restrict__ out)
{
    extern __shared__ char smem[];
    const int      tid  = threadIdx.x;
    const int      lane = tid & 31;
    const int      w    = tid >> 5;
    const uint32_t rank = ctarank();                  // 0..7
    const int clusterRow = (blockIdx.x >> 3) * MROWS; // cluster id * 64
    const uint32_t sb = smem_u32(smem);

    // ---------- zero W+A regions ----------
    for (int i = tid; i < SMEM_BYTES / 4; i += NTHREADS)
        *(uint32_t*)(smem + i * 4) = 0u;
    __syncthreads();

    // ---------- stage W (hi/lo) with permuted j', bias as K-rows 266/267 ----------
    {
        const float* Wh4[4] = {Wgh, Wih, Wfh, Woh};
        const float* Wx4[4] = {Wgx, Wix, Wfx, Wox};
        const float* b4[4]  = {bg, bi, bf, bo};
        #pragma unroll
        for (int g = 0; g < 4; ++g) {
            for (int idx = tid; idx < 32 * HID; idx += NTHREADS) {
                int kk = idx & 31, k = idx >> 5;
                int j = jprime(kk, g);
                float v = Wh4[g][k * HID + (int)rank * 32 + kk];
                __half hi, lo; split16(v, hi, lo);
                uint32_t o = (uint32_t)j * STRB + (uint32_t)(k * 2);
                sts_h16(sb + OFF_WHI + o, hi);
                sts_h16(sb + OFF_WLO + o, lo);
            }
            for (int idx = tid; idx < 32 * EMBD; idx += NTHREADS) {
                int kk = idx & 31, e = idx >> 5;
                int j = jprime(kk, g);
                float v = Wx4[g][e * HID + (int)rank * 32 + kk];
                __half hi, lo; split16(v, hi, lo);
                uint32_t o = (uint32_t)j * STRB + (uint32_t)((256 + e) * 2);
                sts_h16(sb + OFF_WHI + o, hi);
                sts_h16(sb + OFF_WLO + o, lo);
            }
            if (tid < 32) {
                int j = jprime(tid, g);
                float v = b4[g][(int)rank * 32 + tid];
                __half hi, lo; split16(v, hi, lo);
                // bias rows live in W_HI only; A rows 266/267 are 1.0 (hi), 0 (lo)
                sts_h16(sb + OFF_WHI + (uint32_t)j * STRB + 266u * 2, hi);
                sts_h16(sb + OFF_WHI + (uint32_t)j * STRB + 267u * 2, lo);
            }
        }
    }
    // A constant-1 rows for bias (hi region only)
    for (int m = tid; m < MROWS; m += NTHREADS) {
        uint32_t ab = sb + OFF_AHI + (uint32_t)m * STRB;
        sts_h16(ab + 266u * 2, __float2half_rn(1.0f));
        sts_h16(ab + 267u * 2, __float2half_rn(1.0f));
    }
    stage_x(x, emb, clusterRow, 0, tid, sb);   // x for t=0 (h part zero)
    __syncthreads();

    // ---------- GEMM thread mapping ----------
    const int mg = w & 1;          // m slab: rows mg*32..+31
    const int ng = w >> 1;         // n slab: j' ng*32..+31  (kk = ng*8..+7)
    const uint32_t laneOff = (uint32_t)(((((lane >> 3) & 1) * 8 + (lane & 7)) * STRB) + ((lane >> 4) * 16));
    const uint32_t aHiB = sb + OFF_AHI + (uint32_t)(mg * 32) * STRB + laneOff;
    const uint32_t aLoB = aHiB + A_SZ;
    const uint32_t bHiB = sb + OFF_WHI + (uint32_t)(ng * 32) * STRB + laneOff;
    const uint32_t bLoB = bHiB + W_SZ;

    const int dm    = lane >> 2;
    const int codd  = lane & 1;          // 0: row dm, gates (g,i) ; 1: row dm+8, gates (f,o)
    const int chigh = (lane >> 1) & 1;   // 0: kk = nt ; 1: kk = nt+4

    // DSMEM peer bases for A_hi (stagger start by rank)
    uint32_t peerA[CLUSTER];
    #pragma unroll
    for (int p = 0; p < CLUSTER; ++p)
        peerA[p] = mapa_u32(sb + OFF_AHI, (uint32_t)((p + rank) & 7));

    // this thread's h/c cells: rows m(mt), kk k0..k0+3
    const int mrow0 = mg * 32 + dm + (codd ? 8 : 0);      // + mt*16
    const int k0    = (int)rank * 32 + ng * 8 + (chigh ? 4 : 0);
    const uint32_t pushOff0 = (uint32_t)mrow0 * STRB + (uint32_t)(k0 - (int)rank * 32 + (int)rank * 32) * 2;

    float c8[8];
    #pragma unroll
    for (int i = 0; i < 8; ++i) c8[i] = 0.0f;

    for (int t = 0; t < T_STEPS; ++t) {
        // ---------------- GEMM ----------------
        float d[2][4][4];
        #pragma unroll
        for (int a = 0; a < 2; ++a)
            #pragma unroll
            for (int b = 0; b < 4; ++b)
                #pragma unroll
                for (int c = 0; c < 4; ++c) d[a][b][c] = 0.0f;

        #pragma unroll 1
        for (int kc = 0; kc < 17; ++kc) {
            const uint32_t ka = (uint32_t)kc * 32;
            uint32_t ah0[4], ah1[4], al0[4], al1[4];
            uint32_t bh0[4], bh1[4], bl0[4], bl1[4];
            LDSM4(ah0, aHiB + ka); LDSM4(ah1, aHiB + ka + 16 * STRB);
            LDSM4(al0, aLoB + ka); LDSM4(al1, aLoB + ka + 16 * STRB);
            LDSM4(bh0, bHiB + ka); LDSM4(bh1, bHiB + ka + 16 * STRB);
            LDSM4(bl0, bLoB + ka); LDSM4(bl1, bLoB + ka + 16 * STRB);
            #pragma unroll
            for (int mt = 0; mt < 2; ++mt) {
                uint32_t* ah = mt ? ah1 : ah0;
                uint32_t* al = mt ? al1 : al0;
                #pragma unroll
                for (int nt = 0; nt < 4; ++nt) {
                    uint32_t* bh = (nt < 2) ? bh0 : bh1;
                    uint32_t* bl = (nt < 2) ? bl0 : bl1;
                    const int s = nt & 1;
                    MMA(d[mt][nt], ah, bh[s], bh[s + 2]);
                    MMA(d[mt][nt], ah, bl[s], bl[s + 2]);
                    MMA(d[mt][nt], al, bh[s], bh[s + 2]);
                }
            }
        }

        cluster_arrive_();   // done reading A; epilogue is register-only

        // ---------------- register epilogue (shfl gate exchange) ----------------
        uint32_t hpx[2], hpy[2], lpx[2], lpy[2];   // packed h (hi/lo) per mt
        #pragma unroll
        for (int mt = 0; mt < 2; ++mt) {
            __half hh[4], hl[4];
            #pragma unroll
            for (int nt = 0; nt < 4; ++nt) {
                float d0 = d[mt][nt][0], d1 = d[mt][nt][1];
                float d2 = d[mt][nt][2], d3 = d[mt][nt][3];
                float pd0 = __shfl_xor_sync(0xffffffffu, d0, 1);
                float pd1 = __shfl_xor_sync(0xffffffffu, d1, 1);
                float pd2 = __shfl_xor_sync(0xffffffffu, d2, 1);
                float pd3 = __shfl_xor_sync(0xffffffffu, d3, 1);
                float zg, zi, zf, zo;
                if (!codd) { zg = d0;  zi = d1;  zf = pd0; zo = pd1; }
                else       { zg = pd2; zi = pd3; zf = d2;  zo = d3;  }
                float gg = tanh_(zg);
                float ii = sigm(zi);
                float ff = sigm(zf);
                float oo = sigm(zo);
                float cn = fmaf(gg, ii, c8[mt * 4 + nt] * ff);
                c8[mt * 4 + nt] = cn;
                float hn = tanh_(cn) * oo;
                split16(hn, hh[nt], hl[nt]);
            }
            hpx[mt] = (uint32_t)__half_as_ushort(hh[0]) | ((uint32_t)__half_as_ushort(hh[1]) << 16);
            hpy[mt] = (uint32_t)__half_as_ushort(hh[2]) | ((uint32_t)__half_as_ushort(hh[3]) << 16);
            lpx[mt] = (uint32_t)__half_as_ushort(hl[0]) | ((uint32_t)__half_as_ushort(hl[1]) << 16);
            lpy[mt] = (uint32_t)__half_as_ushort(hl[2]) | ((uint32_t)__half_as_ushort(hl[3]) << 16);
        }

        cluster_wait_();     // all CTAs done reading A -> safe to overwrite

        // ---------------- DSMEM push: h -> all 8 cluster A replicas ----------------
        #pragma unroll
        for (int mt = 0; mt < 2; ++mt) {
            uint32_t off = (uint32_t)(mrow0 + mt * 16) * STRB + (uint32_t)(k0 * 2);
            #pragma unroll
            for (int p = 0; p < CLUSTER; ++p) {
                asm volatile("st.shared::cluster.v2.b32 [%0],{%1,%2};"
                             :: "r"(peerA[p] + off), "r"(hpx[mt]), "r"(hpy[mt]) : "memory");
                asm volatile("st.shared::cluster.v2.b32 [%0],{%1,%2};"
                             :: "r"(peerA[p] + off + A_SZ), "r"(lpx[mt]), "r"(lpy[mt]) : "memory");
            }
        }
        if (t != T_STEPS - 1)
            stage_x(x, emb, clusterRow, t + 1, tid, sb);

        cluster_arrive_();   // pushes ordered-before arrive (release)
        cluster_wait_();     // all pushes visible -> next GEMM may read
    }

    // ---------------- final projection: out = h(255) @ Wph + bp ----------------
    if (tid < 8 * NCLS) {
        int mi = tid / NCLS, cl = tid - mi * NCLS;
        int m  = (int)rank * 8 + mi;
        float s = __ldg(&bp[cl]);
        #pragma unroll 4
        for (int k = 0; k < HID; ++k) {
            __half hi = *(const __half*)(smem + OFF_AHI + m * STRB + k * 2);
            __half lo = *(const __half*)(smem + OFF_ALO + m * STRB + k * 2);
            float hv = __half2float(hi) + __half2float(lo);
            s = fmaf(hv, __ldg(&Wph[k * NCLS + cl]), s);
        }
        out[(clusterRow + m) * NCLS + cl] = s;
    }
}

// ---------------- host launch ----------------------
extern "C" void kernel_launch(void* const* d_in, const int* in_sizes, int n_in,
                              void* d_out, int out_size)
{
    const int*   x   = (const int*)  d_in[0];
    const float* emb = (const float*)d_in[1];
    const float* Wgx = (const float*)d_in[2];
    const float* Wgh = (const float*)d_in[3];
    const float* bg  = (const float*)d_in[4];
    const float* Wix = (const float*)d_in[5];
    const float* Wih = (const float*)d_in[6];
    const float* bi  = (const float*)d_in[7];
    const float* Wfx = (const float*)d_in[8];
    const float* Wfh = (const float*)d_in[9];
    const float* bf  = (const float*)d_in[10];
    const float* Wox = (const float*)d_in[11];
    const float* Woh = (const float*)d_in[12];
    const float* bo  = (const float*)d_in[13];
    const float* Wph = (const float*)d_in[14];
    const float* bp  = (const float*)d_in[15];

    cudaFuncSetAttribute(lstm_hmma_kernel,
                         cudaFuncAttributeMaxDynamicSharedMemorySize, SMEM_BYTES);

    lstm_hmma_kernel<<<GRID_X, NTHREADS, SMEM_BYTES>>>(
        x, emb, Wgx, Wgh, bg, Wix, Wih, bi, Wfx, Wfh, bf, Wox, Woh, bo,
        Wph, bp, (float*)d_out);
}